// round 6
// baseline (speedup 1.0000x reference)
#include <cuda_runtime.h>
#include <cuda_bf16.h>
#include <cstdint>
#include <cstddef>

#define N_NODES 16384
#define BM 128
#define SPLITK 8
#define KSPAN (N_NODES / SPLITK)   // 2048

// ---------------- scratch (device globals; no allocation allowed) ----------------
__device__ __nv_bfloat16 g_adj16[(size_t)N_NODES * N_NODES];  // 512MB bf16 adj copy
__device__ uint32_t g_xwB[256 * 64 * 32];        // B blocks: [tk][F][32 kpairs] bf16x2
__device__ float    g_part[SPLITK * N_NODES * 64];
__device__ float    g_colsum[256 * 64];

// ---------------- helpers ----------------
__device__ __forceinline__ uint32_t smem_u32(const void* p) {
    uint32_t a;
    asm("{ .reg .u64 t; cvta.to.shared.u64 t, %1; cvt.u32.u64 %0, t; }" : "=r"(a) : "l"(p));
    return a;
}
__device__ __forceinline__ uint32_t pack_bf16(float lo, float hi) {  // RN, lo in low 16
    uint32_t r; asm("cvt.rn.bf16x2.f32 %0, %1, %2;" : "=r"(r) : "f"(hi), "f"(lo)); return r;
}
__device__ __forceinline__ void mma16(float* c,
                                      uint32_t a0, uint32_t a1, uint32_t a2, uint32_t a3,
                                      uint32_t b0, uint32_t b1) {
    asm volatile("mma.sync.aligned.m16n8k16.row.col.f32.bf16.bf16.f32 "
                 "{%0,%1,%2,%3}, {%4,%5,%6,%7}, {%8,%9}, {%0,%1,%2,%3};"
                 : "+f"(c[0]), "+f"(c[1]), "+f"(c[2]), "+f"(c[3])
                 : "r"(a0), "r"(a1), "r"(a2), "r"(a3), "r"(b0), "r"(b1));
}
__device__ __forceinline__ void cp16(uint32_t smem, const void* gmem) {
    asm volatile("cp.async.cg.shared.global [%0], [%1], 16;" :: "r"(smem), "l"(gmem));
}
#define CP_COMMIT() asm volatile("cp.async.commit_group;")
#define CP_WAIT(n)  asm volatile("cp.async.wait_group %0;" :: "n"(n))

// ---------------- shared mma fragment over one 32-k sub-tile (64B rows) ----------------
template<int F, int NF2>
__device__ __forceinline__ void compute_tile(const uint4* __restrict__ As,
                                             const uint4* __restrict__ Bs,
                                             float c[2][NF2][4],
                                             int wx, int wy, int g, int t) {
#pragma unroll
    for (int mf = 0; mf < 2; mf++) {
        const int r0 = wx * 32 + mf * 16 + g;
        uint4 Alo = As[r0 * 4 + t];
        uint4 Ahi = As[(r0 + 8) * 4 + t];
#pragma unroll
        for (int nf = 0; nf < NF2; nf++) {
            const int n = wy * (F / 2) + nf * 8 + g;
            uint4 Bv = Bs[n * 4 + t];
            mma16(c[mf][nf], Alo.x, Ahi.x, Alo.y, Ahi.y, Bv.x, Bv.y);
            mma16(c[mf][nf], Alo.z, Ahi.z, Alo.w, Ahi.w, Bv.z, Bv.w);
        }
    }
}

template<int F, int NF2>
__device__ __forceinline__ void store_partials(float* __restrict__ part,
                                               float c[2][NF2][4],
                                               int rowBase, int wx, int wy, int g, int t) {
    float* pbase = part + (size_t)blockIdx.y * N_NODES * F;
#pragma unroll
    for (int mf = 0; mf < 2; mf++) {
        const int r0 = rowBase + wx * 32 + mf * 16 + g;
#pragma unroll
        for (int nf = 0; nf < NF2; nf++) {
            const int col = wy * (F / 2) + nf * 8 + 2 * t;
            *reinterpret_cast<float2*>(pbase + (size_t)r0 * F + col) =
                make_float2(c[mf][nf][0], c[mf][nf][1]);
            *reinterpret_cast<float2*>(pbase + (size_t)(r0 + 8) * F + col) =
                make_float2(c[mf][nf][2], c[mf][nf][3]);
        }
    }
}

// ---------------- layer 1: fp32 adj -> bf16 (RN) + GEMM + write g_adj16 (BK=32) ----------------
template<int F>
__global__ __launch_bounds__(256) void adj_gemm_cvt(const float* __restrict__ adj,
                                                    float* __restrict__ part) {
    constexpr int NF2 = F / 16;
    constexpr int NKT = KSPAN / 32;    // 64
    __shared__ __align__(16) uint4 As[2][BM * 4];
    __shared__ __align__(16) uint4 Bs[2][F * 4];

    const int tid = threadIdx.x;
    const int wid = tid >> 5, lane = tid & 31;
    const int g = lane >> 2, t = lane & 3;
    const int wx = wid >> 1, wy = wid & 1;
    const int rowBase = blockIdx.x * BM;
    const int k0 = blockIdx.y * KSPAN;

    float c[2][NF2][4];
#pragma unroll
    for (int mf = 0; mf < 2; mf++)
#pragma unroll
        for (int nf = 0; nf < NF2; nf++)
#pragma unroll
            for (int e = 0; e < 4; e++) c[mf][nf][e] = 0.f;

    // A: 2 bf16 chunks (16B = 8 k) per thread
    int a_r[2], a_c[2];
    const float4* a_src[2];
    uint4* a_dst[2];
#pragma unroll
    for (int i = 0; i < 2; i++) {
        int lin = tid + 256 * i;
        a_r[i] = lin >> 2; a_c[i] = lin & 3;
        a_src[i] = reinterpret_cast<const float4*>(
            adj + (size_t)(rowBase + a_r[i]) * N_NODES + k0 + 8 * a_c[i]);
        a_dst[i] = reinterpret_cast<uint4*>(
            g_adj16 + (size_t)(rowBase + a_r[i]) * N_NODES + k0 + 8 * a_c[i]);
    }
    // B: 1 chunk/thread from blocked layout
    const bool bon = tid < 4 * F;
    const int b_f = bon ? (tid >> 2) : 0, b_jc = tid & 3;
    const uint4* b_base = reinterpret_cast<const uint4*>(g_xwB) + (size_t)(k0 >> 6) * (F * 8);
    const int b_idx = b_f * 8 + b_jc;
    const uint32_t b_smem[2] = { smem_u32(&Bs[0][b_f * 4 + b_jc]), smem_u32(&Bs[1][b_f * 4 + b_jc]) };

    float4 rA[2][2];
#pragma unroll
    for (int i = 0; i < 2; i++) { rA[i][0] = a_src[i][0]; rA[i][1] = a_src[i][1]; }
    if (bon) cp16(b_smem[0], b_base + b_idx);
    CP_COMMIT();

#pragma unroll 1
    for (int ti = 0; ti < NKT; ti++) {
        const int buf = ti & 1;
#pragma unroll
        for (int i = 0; i < 2; i++) {
            uint4 p = make_uint4(pack_bf16(rA[i][0].x, rA[i][0].y), pack_bf16(rA[i][0].z, rA[i][0].w),
                                 pack_bf16(rA[i][1].x, rA[i][1].y), pack_bf16(rA[i][1].z, rA[i][1].w));
            As[buf][a_r[i] * 4 + a_c[i]] = p;
            a_dst[i][(size_t)ti * 4] = p;
        }
        if (ti + 1 < NKT) {
#pragma unroll
            for (int i = 0; i < 2; i++) {
                const float4* s = a_src[i] + (size_t)(ti + 1) * 8;
                rA[i][0] = s[0]; rA[i][1] = s[1];
            }
        }
        CP_WAIT(0);
        __syncthreads();
        if (ti + 1 < NKT) {
            if (bon) cp16(b_smem[buf ^ 1],
                          b_base + (size_t)((ti + 1) >> 1) * (F * 8) + ((ti + 1) & 1) * 4 + b_idx);
            CP_COMMIT();
        }
        compute_tile<F, NF2>(As[buf], Bs[buf], c, wx, wy, g, t);
    }
    store_partials<F, NF2>(part, c, rowBase, wx, wy, g, t);
}

// ---------------- layers 2/3: bf16 adj, cp.async, BK=64 (two 32-k sub-tiles) ----------------
template<int F>
__global__ __launch_bounds__(256) void adj_gemm_cp(float* __restrict__ part) {
    constexpr int NF2 = F / 16;
    constexpr int NKT = KSPAN / 64;     // 32
    __shared__ __align__(16) uint4 As[2][2 * BM * 4];   // [stage][sub*512 + row*4 + cc]
    __shared__ __align__(16) uint4 Bs[2][2 * F * 4];    // [stage][sub*F*4 + f*4 + cc]

    const int tid = threadIdx.x;
    const int wid = tid >> 5, lane = tid & 31;
    const int g = lane >> 2, t = lane & 3;
    const int wx = wid >> 1, wy = wid & 1;
    const int rowBase = blockIdx.x * BM;
    const int k0 = blockIdx.y * KSPAN;

    float c[2][NF2][4];
#pragma unroll
    for (int mf = 0; mf < 2; mf++)
#pragma unroll
        for (int nf = 0; nf < NF2; nf++)
#pragma unroll
            for (int e = 0; e < 4; e++) c[mf][nf][e] = 0.f;

    // A: 4 chunks/thread (128 rows x 8 chunks of 16B)
    const __nv_bfloat16* a_src[4];
    uint32_t a_sm[4][2];
#pragma unroll
    for (int i = 0; i < 4; i++) {
        int lin = tid + 256 * i;
        int row = lin >> 3, ch = lin & 7;
        a_src[i] = g_adj16 + (size_t)(rowBase + row) * N_NODES + k0 + 8 * ch;
        int off = (ch >> 2) * 512 + row * 4 + (ch & 3);
        a_sm[i][0] = smem_u32(&As[0][off]);
        a_sm[i][1] = smem_u32(&As[1][off]);
    }
    // B: 2 chunks/thread (F*8 uint4 per tile, linear source)
    const uint4* b_base = reinterpret_cast<const uint4*>(g_xwB) + (size_t)(k0 >> 6) * (F * 8);
    bool bact[2]; int b_m[2];
    uint32_t b_sm[2][2];
#pragma unroll
    for (int i = 0; i < 2; i++) {
        int m = tid + 256 * i;
        bact[i] = m < F * 8;
        int mm = bact[i] ? m : 0;
        int f = mm >> 3, w4 = mm & 7;
        int off = (w4 >> 2) * (F * 4) + f * 4 + (w4 & 3);
        b_sm[i][0] = smem_u32(&Bs[0][off]);
        b_sm[i][1] = smem_u32(&Bs[1][off]);
        b_m[i] = mm;
    }

    auto issue = [&](int ti, int s) {
#pragma unroll
        for (int i = 0; i < 4; i++) cp16(a_sm[i][s], a_src[i] + (size_t)ti * 64);
#pragma unroll
        for (int i = 0; i < 2; i++)
            if (bact[i]) cp16(b_sm[i][s], b_base + (size_t)ti * (F * 8) + b_m[i]);
        CP_COMMIT();
    };

    issue(0, 0);

#pragma unroll 1
    for (int ti = 0; ti < NKT; ti++) {
        const int s = ti & 1;
        CP_WAIT(0);
        __syncthreads();
        if (ti + 1 < NKT) issue(ti + 1, s ^ 1);
        compute_tile<F, NF2>(&As[s][0],   &Bs[s][0],     c, wx, wy, g, t);
        compute_tile<F, NF2>(&As[s][512], &Bs[s][F * 4], c, wx, wy, g, t);
    }
    store_partials<F, NF2>(part, c, rowBase, wx, wy, g, t);
}

// ---------------- fused: xw1 = x @ W1, packed into blocked B layout ----------------
__global__ __launch_bounds__(256) void fuse_first(const float* __restrict__ x,
                                                  const float* __restrict__ W1) {
    __shared__ float Ws[128 * 32];       // 16KB
    __shared__ uint32_t stage[32 * 32];  // 4KB
    const int tid = threadIdx.x;
    for (int i = tid; i < 128 * 32 / 4; i += 256)
        reinterpret_cast<float4*>(Ws)[i] = reinterpret_cast<const float4*>(W1)[i];
    __syncthreads();

    const int rp = tid >> 3, cgi = tid & 7;
    const int c0 = cgi * 4;
    const int r0 = blockIdx.x * 64 + 2 * rp;
    const float4* x0 = reinterpret_cast<const float4*>(x + (size_t)r0 * 128);
    const float4* x1 = reinterpret_cast<const float4*>(x + (size_t)(r0 + 1) * 128);
    float acc0[4] = {0.f, 0.f, 0.f, 0.f}, acc1[4] = {0.f, 0.f, 0.f, 0.f};
#pragma unroll 8
    for (int k4 = 0; k4 < 32; k4++) {
        float4 a = __ldg(&x0[k4]), b = __ldg(&x1[k4]);
#pragma unroll
        for (int e = 0; e < 4; e++) {
            float ae = (e == 0) ? a.x : (e == 1) ? a.y : (e == 2) ? a.z : a.w;
            float be = (e == 0) ? b.x : (e == 1) ? b.y : (e == 2) ? b.z : b.w;
            float4 wv = *reinterpret_cast<const float4*>(&Ws[(k4 * 4 + e) * 32 + c0]);
            acc0[0] += ae * wv.x; acc0[1] += ae * wv.y; acc0[2] += ae * wv.z; acc0[3] += ae * wv.w;
            acc1[0] += be * wv.x; acc1[1] += be * wv.y; acc1[2] += be * wv.z; acc1[3] += be * wv.w;
        }
    }
#pragma unroll
    for (int cc = 0; cc < 4; cc++)
        stage[(c0 + cc) * 32 + rp] = pack_bf16(acc0[cc], acc1[cc]);
    __syncthreads();
    uint4* out = reinterpret_cast<uint4*>(g_xwB + blockIdx.x * 32 * 32);
    out[tid] = reinterpret_cast<const uint4*>(stage)[tid];
}

// ---------------- fused: combine split-K + bias + relu + @W_next + pack to B layout ----------------
template<int FI, int FO>
__global__ __launch_bounds__(256) void fuse_next(const float* __restrict__ part,
                                                 const float* __restrict__ bias,
                                                 const float* __restrict__ W) {
    __shared__ float Ws[FI * FO];
    __shared__ float hs[64 * FI];
    __shared__ uint32_t stage[FO * 32];
    const int tid = threadIdx.x;
    for (int i = tid; i < FI * FO / 4; i += 256)
        reinterpret_cast<float4*>(Ws)[i] = reinterpret_cast<const float4*>(W)[i];

    // h = relu(sum_sk part + bias)
    {
        const int row = tid >> 2, q = tid & 3;
        const int f0 = q * (FI / 4);
        const int gr = blockIdx.x * 64 + row;
        float acc[FI / 4];
#pragma unroll
        for (int j = 0; j < FI / 4; j++) acc[j] = bias[f0 + j];
#pragma unroll
        for (int sk = 0; sk < SPLITK; sk++) {
            const float* p = part + ((size_t)sk * N_NODES + gr) * FI + f0;
#pragma unroll
            for (int j4 = 0; j4 < FI / 16; j4++) {
                float4 v = *reinterpret_cast<const float4*>(p + 4 * j4);
                acc[j4 * 4 + 0] += v.x; acc[j4 * 4 + 1] += v.y;
                acc[j4 * 4 + 2] += v.z; acc[j4 * 4 + 3] += v.w;
            }
        }
#pragma unroll
        for (int j = 0; j < FI / 4; j++) hs[row * FI + f0 + j] = fmaxf(acc[j], 0.f);
    }
    __syncthreads();

    // xw = h @ W, packed into row-pair bf16x2
    {
        const int rp = tid >> 3, cgi = tid & 7;
        const int c0 = cgi * (FO / 8);
        float a0c[FO / 8], a1c[FO / 8];
#pragma unroll
        for (int cc = 0; cc < FO / 8; cc++) { a0c[cc] = 0.f; a1c[cc] = 0.f; }
#pragma unroll 4
        for (int k = 0; k < FI; k++) {
            float a0 = hs[(2 * rp) * FI + k];
            float a1 = hs[(2 * rp + 1) * FI + k];
#pragma unroll
            for (int cc = 0; cc < FO / 8; cc++) {
                float w = Ws[k * FO + c0 + cc];
                a0c[cc] += a0 * w; a1c[cc] += a1 * w;
            }
        }
#pragma unroll
        for (int cc = 0; cc < FO / 8; cc++)
            stage[(c0 + cc) * 32 + rp] = pack_bf16(a0c[cc], a1c[cc]);
    }
    __syncthreads();
    uint4* out = reinterpret_cast<uint4*>(g_xwB + blockIdx.x * FO * 32);
#pragma unroll
    for (int i = tid; i < FO * 8; i += 256)
        out[i] = reinterpret_cast<const uint4*>(stage)[i];
}

// ---------------- layer-3 combine + deterministic column reduction (F=64) ----------------
__global__ __launch_bounds__(256) void combine_reduce(const float* __restrict__ part,
                                                      const float* __restrict__ bias,
                                                      float* __restrict__ colsum) {
    __shared__ float red[4][64];
    const int tid = threadIdx.x;
    const int c = tid & 63, rg = tid >> 6;
    const int rowBase = blockIdx.x * 64;
    const float b = bias[c];
    float s = 0.f;
#pragma unroll 4
    for (int i = 0; i < 16; i++) {
        const int row = rowBase + rg + 4 * i;
        float v = 0.f;
#pragma unroll
        for (int sk = 0; sk < SPLITK; sk++)
            v += part[((size_t)sk * N_NODES + row) * 64 + c];
        s += fmaxf(v + b, 0.f);
    }
    red[rg][c] = s;
    __syncthreads();
    if (rg == 0)
        colsum[blockIdx.x * 64 + c] = red[0][c] + red[1][c] + red[2][c] + red[3][c];
}

// ---------------- readout + MLP head + softmax ----------------
__global__ void head_kernel(const float* __restrict__ colsum,
                            const float* __restrict__ fcW1, const float* __restrict__ fcb1,
                            const float* __restrict__ fcW2, const float* __restrict__ fcb2,
                            float* __restrict__ out) {
    __shared__ float mean_s[64];
    __shared__ float z1_s[32];
    int t = threadIdx.x;  // 64 threads
    float s = 0.f;
    for (int b = 0; b < 256; b++) s += colsum[b * 64 + t];
    mean_s[t] = s * (1.0f / N_NODES);
    __syncthreads();
    if (t < 32) {
        float a = 0.f;
#pragma unroll
        for (int c = 0; c < 64; c++) a += mean_s[c] * fcW1[c * 32 + t];
        z1_s[t] = fmaxf(a + fcb1[t], 0.f);
    }
    __syncthreads();
    if (t == 0) {
        float z0 = fcb2[0], z1 = fcb2[1];
#pragma unroll
        for (int j = 0; j < 32; j++) {
            z0 += z1_s[j] * fcW2[j * 2 + 0];
            z1 += z1_s[j] * fcW2[j * 2 + 1];
        }
        float m  = fmaxf(z0, z1);
        float e0 = expf(z0 - m), e1 = expf(z1 - m);
        float inv = 1.0f / (e0 + e1);
        out[0] = e0 * inv;
        out[1] = e1 * inv;
    }
}

// ---------------- launch ----------------
extern "C" void kernel_launch(void* const* d_in, const int* in_sizes, int n_in,
                              void* d_out, int out_size) {
    const float* x    = (const float*)d_in[0];
    const float* adj  = (const float*)d_in[1];
    // d_in[2] = idx_map (unused by the reference)
    const float* W1   = (const float*)d_in[3];
    const float* b1   = (const float*)d_in[4];
    const float* W2   = (const float*)d_in[5];
    const float* b2   = (const float*)d_in[6];
    const float* W3   = (const float*)d_in[7];
    const float* b3   = (const float*)d_in[8];
    const float* fcW1 = (const float*)d_in[9];
    const float* fcb1 = (const float*)d_in[10];
    const float* fcW2 = (const float*)d_in[11];
    const float* fcb2 = (const float*)d_in[12];
    float* out = (float*)d_out;

    float *part, *colsum;
    cudaGetSymbolAddress((void**)&part, g_part);
    cudaGetSymbolAddress((void**)&colsum, g_colsum);

    dim3 agrid(N_NODES / BM, SPLITK);

    fuse_first<<<256, 256>>>(x, W1);
    adj_gemm_cvt<32><<<agrid, 256>>>(adj, part);
    fuse_next<32, 48><<<256, 256>>>(part, b1, W2);
    adj_gemm_cp<48><<<agrid, 256>>>(part);
    fuse_next<48, 64><<<256, 256>>>(part, b2, W3);
    adj_gemm_cp<64><<<agrid, 256>>>(part);
    combine_reduce<<<256, 256>>>(part, b3, colsum);
    head_kernel<<<1, 64>>>(colsum, fcW1, fcb1, fcW2, fcb2, out);
}

// round 7
// speedup vs baseline: 1.1377x; 1.1377x over previous
#include <cuda_runtime.h>
#include <cuda_bf16.h>
#include <cstdint>
#include <cstddef>

#define N_NODES 16384
#define BM 128
#define SPLITK 8
#define KSPAN (N_NODES / SPLITK)   // 2048

// ---------------- scratch (device globals; no allocation allowed) ----------------
__device__ __nv_bfloat16 g_adj16[(size_t)N_NODES * N_NODES];  // 512MB bf16 adj copy
__device__ uint32_t g_xwB[256 * 64 * 32];        // B blocks: [tk64][F][32 kpairs] bf16x2
__device__ float    g_part[SPLITK * N_NODES * 64];
__device__ float    g_colsum[256 * 64];

// ---------------- helpers ----------------
__device__ __forceinline__ uint32_t smem_u32(const void* p) {
    uint32_t a;
    asm("{ .reg .u64 t; cvta.to.shared.u64 t, %1; cvt.u32.u64 %0, t; }" : "=r"(a) : "l"(p));
    return a;
}
__device__ __forceinline__ uint32_t pack_bf16(float lo, float hi) {  // RN, lo in low 16
    uint32_t r; asm("cvt.rn.bf16x2.f32 %0, %1, %2;" : "=r"(r) : "f"(hi), "f"(lo)); return r;
}
__device__ __forceinline__ void mma16(float* c,
                                      uint32_t a0, uint32_t a1, uint32_t a2, uint32_t a3,
                                      uint32_t b0, uint32_t b1) {
    asm volatile("mma.sync.aligned.m16n8k16.row.col.f32.bf16.bf16.f32 "
                 "{%0,%1,%2,%3}, {%4,%5,%6,%7}, {%8,%9}, {%0,%1,%2,%3};"
                 : "+f"(c[0]), "+f"(c[1]), "+f"(c[2]), "+f"(c[3])
                 : "r"(a0), "r"(a1), "r"(a2), "r"(a3), "r"(b0), "r"(b1));
}
__device__ __forceinline__ void cp16(uint32_t smem, const void* gmem) {
    asm volatile("cp.async.cg.shared.global [%0], [%1], 16;" :: "r"(smem), "l"(gmem));
}
#define CP_COMMIT() asm volatile("cp.async.commit_group;")
#define CP_WAIT(n)  asm volatile("cp.async.wait_group %0;" :: "n"(n))

// ---------------- shared mma fragment over one 32-k sub-tile (bf16, 64B rows) ----------------
template<int F, int NF2>
__device__ __forceinline__ void compute_tile(const uint4* __restrict__ As,
                                             const uint4* __restrict__ Bs,
                                             float c[2][NF2][4],
                                             int wx, int wy, int g, int t) {
#pragma unroll
    for (int mf = 0; mf < 2; mf++) {
        const int r0 = wx * 32 + mf * 16 + g;
        uint4 Alo = As[r0 * 4 + t];
        uint4 Ahi = As[(r0 + 8) * 4 + t];
#pragma unroll
        for (int nf = 0; nf < NF2; nf++) {
            const int n = wy * (F / 2) + nf * 8 + g;
            uint4 Bv = Bs[n * 4 + t];
            mma16(c[mf][nf], Alo.x, Ahi.x, Alo.y, Ahi.y, Bv.x, Bv.y);
            mma16(c[mf][nf], Alo.z, Ahi.z, Alo.w, Ahi.w, Bv.z, Bv.w);
        }
    }
}

template<int F, int NF2>
__device__ __forceinline__ void store_partials(float* __restrict__ part,
                                               float c[2][NF2][4],
                                               int rowBase, int wx, int wy, int g, int t) {
    float* pbase = part + (size_t)blockIdx.y * N_NODES * F;
#pragma unroll
    for (int mf = 0; mf < 2; mf++) {
        const int r0 = rowBase + wx * 32 + mf * 16 + g;
#pragma unroll
        for (int nf = 0; nf < NF2; nf++) {
            const int col = wy * (F / 2) + nf * 8 + 2 * t;
            *reinterpret_cast<float2*>(pbase + (size_t)r0 * F + col) =
                make_float2(c[mf][nf][0], c[mf][nf][1]);
            *reinterpret_cast<float2*>(pbase + (size_t)(r0 + 8) * F + col) =
                make_float2(c[mf][nf][2], c[mf][nf][3]);
        }
    }
}

// ---------------- layer 1: cp.async fp32 adj -> frag cvt + GEMM + bf16 copy (3 stages) ----------------
template<int F>
__global__ __launch_bounds__(256) void adj_gemm_cvt(const float* __restrict__ adj,
                                                    float* __restrict__ part) {
    constexpr int NF2 = F / 16;
    constexpr int NKT = KSPAN / 32;    // 64
    constexpr int S = 3;
    __shared__ __align__(16) float4 As[S][128 * 8];  // fp32 tile, 16KB/stage
    __shared__ __align__(16) uint4  Bs[S][F * 4];
    constexpr uint32_t A_STRIDE = 128 * 8 * sizeof(float4);
    constexpr uint32_t B_STRIDE = F * 4 * sizeof(uint4);

    const int tid = threadIdx.x;
    const int wid = tid >> 5, lane = tid & 31;
    const int g = lane >> 2, t = lane & 3;
    const int wx = wid >> 1, wy = wid & 1;
    const int rowBase = blockIdx.x * BM;
    const int k0 = blockIdx.y * KSPAN;

    float c[2][NF2][4];
#pragma unroll
    for (int mf = 0; mf < 2; mf++)
#pragma unroll
        for (int nf = 0; nf < NF2; nf++)
#pragma unroll
            for (int e = 0; e < 4; e++) c[mf][nf][e] = 0.f;

    // A: 4 cp16/thread (128 rows x 8 float4-chunks)
    const float4* a_src[4];
    uint32_t a_sm0[4];
#pragma unroll
    for (int i = 0; i < 4; i++) {
        int lin = tid + 256 * i;
        int row = lin >> 3, ch = lin & 7;
        a_src[i] = reinterpret_cast<const float4*>(
            adj + (size_t)(rowBase + row) * N_NODES + k0) + ch;
        a_sm0[i] = smem_u32(&As[0][row * 8 + ch]);
    }
    // B: 1 cp16/thread from blocked layout
    const bool bon = tid < 4 * F;
    const int b_f = bon ? (tid >> 2) : 0, b_jc = tid & 3;
    const uint4* b_base = reinterpret_cast<const uint4*>(g_xwB) + (size_t)(k0 >> 6) * (F * 8);
    const uint32_t b_sm0 = smem_u32(&Bs[0][b_f * 4 + b_jc]);
    const int b_fix = b_f * 8 + b_jc;

    auto issue = [&](int ti, int s) {
#pragma unroll
        for (int i = 0; i < 4; i++) cp16(a_sm0[i] + s * A_STRIDE, a_src[i] + (size_t)ti * 8);
        if (bon) cp16(b_sm0 + s * B_STRIDE,
                      b_base + (size_t)(ti >> 1) * (F * 8) + ((ti & 1) * 4) + b_fix);
        CP_COMMIT();
    };

    issue(0, 0);
    issue(1, 1);

    // copy map: 2 float4-pairs/thread -> 2 STG.128 bf16
    const int cj0 = tid, cj1 = tid + 256;

#pragma unroll 1
    for (int ti = 0; ti < NKT; ti++) {
        const int s = ti % 3;
        if (ti + 2 < NKT) { CP_WAIT(1); } else { CP_WAIT(0); }
        __syncthreads();
        if (ti + 2 < NKT) issue(ti + 2, (ti + 2) % 3);

        // bf16 copy to g_adj16 (from smem)
#pragma unroll
        for (int i = 0; i < 2; i++) {
            int j = (i == 0) ? cj0 : cj1;                 // 0..511
            float4 u = As[s][2 * j], v = As[s][2 * j + 1];
            uint4 p = make_uint4(pack_bf16(u.x, u.y), pack_bf16(u.z, u.w),
                                 pack_bf16(v.x, v.y), pack_bf16(v.z, v.w));
            int row = j >> 2;
            *reinterpret_cast<uint4*>(
                g_adj16 + (size_t)(rowBase + row) * N_NODES + k0 + ti * 32 + (j & 3) * 8) = p;
        }

        // compute: build bf16 fragments from fp32 smem
#pragma unroll
        for (int mf = 0; mf < 2; mf++) {
            const int r0 = wx * 32 + mf * 16 + g;
            float4 a0 = As[s][r0 * 8 + 2 * t],       a1 = As[s][r0 * 8 + 2 * t + 1];
            float4 h0 = As[s][(r0 + 8) * 8 + 2 * t], h1 = As[s][(r0 + 8) * 8 + 2 * t + 1];
            uint32_t alo0 = pack_bf16(a0.x, a0.y), alo1 = pack_bf16(a0.z, a0.w);
            uint32_t alo2 = pack_bf16(a1.x, a1.y), alo3 = pack_bf16(a1.z, a1.w);
            uint32_t ahi0 = pack_bf16(h0.x, h0.y), ahi1 = pack_bf16(h0.z, h0.w);
            uint32_t ahi2 = pack_bf16(h1.x, h1.y), ahi3 = pack_bf16(h1.z, h1.w);
#pragma unroll
            for (int nf = 0; nf < NF2; nf++) {
                const int n = wy * (F / 2) + nf * 8 + g;
                uint4 Bv = Bs[s][n * 4 + t];
                mma16(c[mf][nf], alo0, ahi0, alo1, ahi1, Bv.x, Bv.y);
                mma16(c[mf][nf], alo2, ahi2, alo3, ahi3, Bv.z, Bv.w);
            }
        }
    }
    store_partials<F, NF2>(part, c, rowBase, wx, wy, g, t);
}

// ---------------- layers 2/3: bf16 adj, 5-stage cp.async pipeline, BK=32 ----------------
template<int F>
__global__ __launch_bounds__(256) void adj_gemm_cp(float* __restrict__ part) {
    constexpr int NF2 = F / 16;
    constexpr int NKT = KSPAN / 32;    // 64
    constexpr int S = 5;
    __shared__ __align__(16) uint4 As[S][BM * 4];   // 8KB/stage
    __shared__ __align__(16) uint4 Bs[S][F * 4];
    constexpr uint32_t A_STRIDE = BM * 4 * sizeof(uint4);
    constexpr uint32_t B_STRIDE = F * 4 * sizeof(uint4);

    const int tid = threadIdx.x;
    const int wid = tid >> 5, lane = tid & 31;
    const int g = lane >> 2, t = lane & 3;
    const int wx = wid >> 1, wy = wid & 1;
    const int rowBase = blockIdx.x * BM;
    const int k0 = blockIdx.y * KSPAN;

    float c[2][NF2][4];
#pragma unroll
    for (int mf = 0; mf < 2; mf++)
#pragma unroll
        for (int nf = 0; nf < NF2; nf++)
#pragma unroll
            for (int e = 0; e < 4; e++) c[mf][nf][e] = 0.f;

    // A: 2 cp16/thread (128 rows x 4 chunks of 16B bf16)
    const __nv_bfloat16* a_src[2];
    uint32_t a_sm0[2];
#pragma unroll
    for (int i = 0; i < 2; i++) {
        int lin = tid + 256 * i;
        int row = lin >> 2, ch = lin & 3;
        a_src[i] = g_adj16 + (size_t)(rowBase + row) * N_NODES + k0 + 8 * ch;
        a_sm0[i] = smem_u32(&As[0][row * 4 + ch]);
    }
    // B: 1 cp16/thread
    const bool bon = tid < 4 * F;
    const int b_f = bon ? (tid >> 2) : 0, b_jc = tid & 3;
    const uint4* b_base = reinterpret_cast<const uint4*>(g_xwB) + (size_t)(k0 >> 6) * (F * 8);
    const uint32_t b_sm0 = smem_u32(&Bs[0][b_f * 4 + b_jc]);
    const int b_fix = b_f * 8 + b_jc;

    auto issue = [&](int ti, int s) {
#pragma unroll
        for (int i = 0; i < 2; i++) cp16(a_sm0[i] + s * A_STRIDE, a_src[i] + (size_t)ti * 32);
        if (bon) cp16(b_sm0 + s * B_STRIDE,
                      b_base + (size_t)(ti >> 1) * (F * 8) + ((ti & 1) * 4) + b_fix);
        CP_COMMIT();
    };

#pragma unroll
    for (int p = 0; p < S - 1; p++) issue(p, p);

#pragma unroll 1
    for (int ti = 0; ti < NKT; ti++) {
        const int s = ti % S;
        if (ti + S - 1 < NKT) { CP_WAIT(S - 2); } else { CP_WAIT(0); }
        __syncthreads();
        if (ti + S - 1 < NKT) issue(ti + S - 1, (ti + S - 1) % S);
        compute_tile<F, NF2>(As[s], Bs[s], c, wx, wy, g, t);
    }
    store_partials<F, NF2>(part, c, rowBase, wx, wy, g, t);
}

// ---------------- fused: xw1 = x @ W1, packed into blocked B layout ----------------
__global__ __launch_bounds__(256) void fuse_first(const float* __restrict__ x,
                                                  const float* __restrict__ W1) {
    __shared__ float Ws[128 * 32];
    __shared__ uint32_t stage[32 * 32];
    const int tid = threadIdx.x;
    for (int i = tid; i < 128 * 32 / 4; i += 256)
        reinterpret_cast<float4*>(Ws)[i] = reinterpret_cast<const float4*>(W1)[i];
    __syncthreads();

    const int rp = tid >> 3, cgi = tid & 7;
    const int c0 = cgi * 4;
    const int r0 = blockIdx.x * 64 + 2 * rp;
    const float4* x0 = reinterpret_cast<const float4*>(x + (size_t)r0 * 128);
    const float4* x1 = reinterpret_cast<const float4*>(x + (size_t)(r0 + 1) * 128);
    float acc0[4] = {0.f, 0.f, 0.f, 0.f}, acc1[4] = {0.f, 0.f, 0.f, 0.f};
#pragma unroll 8
    for (int k4 = 0; k4 < 32; k4++) {
        float4 a = __ldg(&x0[k4]), b = __ldg(&x1[k4]);
#pragma unroll
        for (int e = 0; e < 4; e++) {
            float ae = (e == 0) ? a.x : (e == 1) ? a.y : (e == 2) ? a.z : a.w;
            float be = (e == 0) ? b.x : (e == 1) ? b.y : (e == 2) ? b.z : b.w;
            float4 wv = *reinterpret_cast<const float4*>(&Ws[(k4 * 4 + e) * 32 + c0]);
            acc0[0] += ae * wv.x; acc0[1] += ae * wv.y; acc0[2] += ae * wv.z; acc0[3] += ae * wv.w;
            acc1[0] += be * wv.x; acc1[1] += be * wv.y; acc1[2] += be * wv.z; acc1[3] += be * wv.w;
        }
    }
#pragma unroll
    for (int cc = 0; cc < 4; cc++)
        stage[(c0 + cc) * 32 + rp] = pack_bf16(acc0[cc], acc1[cc]);
    __syncthreads();
    uint4* out = reinterpret_cast<uint4*>(g_xwB + blockIdx.x * 32 * 32);
    out[tid] = reinterpret_cast<const uint4*>(stage)[tid];
}

// ---------------- fused: combine split-K + bias + relu + @W_next + pack to B layout ----------------
template<int FI, int FO>
__global__ __launch_bounds__(256) void fuse_next(const float* __restrict__ part,
                                                 const float* __restrict__ bias,
                                                 const float* __restrict__ W) {
    __shared__ float Ws[FI * FO];
    __shared__ float hs[64 * FI];
    __shared__ uint32_t stage[FO * 32];
    const int tid = threadIdx.x;
    for (int i = tid; i < FI * FO / 4; i += 256)
        reinterpret_cast<float4*>(Ws)[i] = reinterpret_cast<const float4*>(W)[i];

    {
        const int row = tid >> 2, q = tid & 3;
        const int f0 = q * (FI / 4);
        const int gr = blockIdx.x * 64 + row;
        float acc[FI / 4];
#pragma unroll
        for (int j = 0; j < FI / 4; j++) acc[j] = bias[f0 + j];
#pragma unroll
        for (int sk = 0; sk < SPLITK; sk++) {
            const float* p = part + ((size_t)sk * N_NODES + gr) * FI + f0;
#pragma unroll
            for (int j4 = 0; j4 < FI / 16; j4++) {
                float4 v = *reinterpret_cast<const float4*>(p + 4 * j4);
                acc[j4 * 4 + 0] += v.x; acc[j4 * 4 + 1] += v.y;
                acc[j4 * 4 + 2] += v.z; acc[j4 * 4 + 3] += v.w;
            }
        }
#pragma unroll
        for (int j = 0; j < FI / 4; j++) hs[row * FI + f0 + j] = fmaxf(acc[j], 0.f);
    }
    __syncthreads();

    {
        const int rp = tid >> 3, cgi = tid & 7;
        const int c0 = cgi * (FO / 8);
        float a0c[FO / 8], a1c[FO / 8];
#pragma unroll
        for (int cc = 0; cc < FO / 8; cc++) { a0c[cc] = 0.f; a1c[cc] = 0.f; }
#pragma unroll 4
        for (int k = 0; k < FI; k++) {
            float a0 = hs[(2 * rp) * FI + k];
            float a1 = hs[(2 * rp + 1) * FI + k];
#pragma unroll
            for (int cc = 0; cc < FO / 8; cc++) {
                float w = Ws[k * FO + c0 + cc];
                a0c[cc] += a0 * w; a1c[cc] += a1 * w;
            }
        }
#pragma unroll
        for (int cc = 0; cc < FO / 8; cc++)
            stage[(c0 + cc) * 32 + rp] = pack_bf16(a0c[cc], a1c[cc]);
    }
    __syncthreads();
    uint4* out = reinterpret_cast<uint4*>(g_xwB + blockIdx.x * FO * 32);
#pragma unroll
    for (int i = tid; i < FO * 8; i += 256)
        out[i] = reinterpret_cast<const uint4*>(stage)[i];
}

// ---------------- layer-3 combine + deterministic column reduction (F=64) ----------------
__global__ __launch_bounds__(256) void combine_reduce(const float* __restrict__ part,
                                                      const float* __restrict__ bias,
                                                      float* __restrict__ colsum) {
    __shared__ float red[4][64];
    const int tid = threadIdx.x;
    const int c = tid & 63, rg = tid >> 6;
    const int rowBase = blockIdx.x * 64;
    const float b = bias[c];
    float s = 0.f;
#pragma unroll 4
    for (int i = 0; i < 16; i++) {
        const int row = rowBase + rg + 4 * i;
        float v = 0.f;
#pragma unroll
        for (int sk = 0; sk < SPLITK; sk++)
            v += part[((size_t)sk * N_NODES + row) * 64 + c];
        s += fmaxf(v + b, 0.f);
    }
    red[rg][c] = s;
    __syncthreads();
    if (rg == 0)
        colsum[blockIdx.x * 64 + c] = red[0][c] + red[1][c] + red[2][c] + red[3][c];
}

// ---------------- readout + MLP head + softmax ----------------
__global__ void head_kernel(const float* __restrict__ colsum,
                            const float* __restrict__ fcW1, const float* __restrict__ fcb1,
                            const float* __restrict__ fcW2, const float* __restrict__ fcb2,
                            float* __restrict__ out) {
    __shared__ float mean_s[64];
    __shared__ float z1_s[32];
    int t = threadIdx.x;  // 64 threads
    float s = 0.f;
    for (int b = 0; b < 256; b++) s += colsum[b * 64 + t];
    mean_s[t] = s * (1.0f / N_NODES);
    __syncthreads();
    if (t < 32) {
        float a = 0.f;
#pragma unroll
        for (int c = 0; c < 64; c++) a += mean_s[c] * fcW1[c * 32 + t];
        z1_s[t] = fmaxf(a + fcb1[t], 0.f);
    }
    __syncthreads();
    if (t == 0) {
        float z0 = fcb2[0], z1 = fcb2[1];
#pragma unroll
        for (int j = 0; j < 32; j++) {
            z0 += z1_s[j] * fcW2[j * 2 + 0];
            z1 += z1_s[j] * fcW2[j * 2 + 1];
        }
        float m  = fmaxf(z0, z1);
        float e0 = expf(z0 - m), e1 = expf(z1 - m);
        float inv = 1.0f / (e0 + e1);
        out[0] = e0 * inv;
        out[1] = e1 * inv;
    }
}

// ---------------- launch ----------------
extern "C" void kernel_launch(void* const* d_in, const int* in_sizes, int n_in,
                              void* d_out, int out_size) {
    const float* x    = (const float*)d_in[0];
    const float* adj  = (const float*)d_in[1];
    // d_in[2] = idx_map (unused by the reference)
    const float* W1   = (const float*)d_in[3];
    const float* b1   = (const float*)d_in[4];
    const float* W2   = (const float*)d_in[5];
    const float* b2   = (const float*)d_in[6];
    const float* W3   = (const float*)d_in[7];
    const float* b3   = (const float*)d_in[8];
    const float* fcW1 = (const float*)d_in[9];
    const float* fcb1 = (const float*)d_in[10];
    const float* fcW2 = (const float*)d_in[11];
    const float* fcb2 = (const float*)d_in[12];
    float* out = (float*)d_out;

    float *part, *colsum;
    cudaGetSymbolAddress((void**)&part, g_part);
    cudaGetSymbolAddress((void**)&colsum, g_colsum);

    dim3 agrid(N_NODES / BM, SPLITK);

    fuse_first<<<256, 256>>>(x, W1);
    adj_gemm_cvt<32><<<agrid, 256>>>(adj, part);
    fuse_next<32, 48><<<256, 256>>>(part, b1, W2);
    adj_gemm_cp<48><<<agrid, 256>>>(part);
    fuse_next<48, 64><<<256, 256>>>(part, b2, W3);
    adj_gemm_cp<64><<<agrid, 256>>>(part);
    combine_reduce<<<256, 256>>>(part, b3, colsum);
    head_kernel<<<1, 64>>>(colsum, fcW1, fcb1, fcW2, fcb2, out);
}

// round 8
// speedup vs baseline: 1.1639x; 1.0230x over previous
#include <cuda_runtime.h>
#include <cuda_bf16.h>
#include <cstdint>
#include <cstddef>

#define N_NODES 16384
#define BM 128
#define SPLITK 8
#define KSPAN (N_NODES / SPLITK)   // 2048

// ---------------- scratch (device globals; no allocation allowed) ----------------
__device__ __nv_bfloat16 g_adj16[(size_t)N_NODES * N_NODES];  // 512MB bf16 adj copy
__device__ uint32_t g_xwB[256 * 64 * 32];        // B blocks: [tk64][F][32 kpairs] bf16x2
__device__ float    g_part[SPLITK * N_NODES * 64];
__device__ float    g_colsum[256 * 64];

// ---------------- helpers ----------------
__device__ __forceinline__ uint32_t smem_u32(const void* p) {
    uint32_t a;
    asm("{ .reg .u64 t; cvta.to.shared.u64 t, %1; cvt.u32.u64 %0, t; }" : "=r"(a) : "l"(p));
    return a;
}
__device__ __forceinline__ uint32_t pack_bf16(float lo, float hi) {  // RN, lo in low 16
    uint32_t r; asm("cvt.rn.bf16x2.f32 %0, %1, %2;" : "=r"(r) : "f"(hi), "f"(lo)); return r;
}
__device__ __forceinline__ void mma16(float* c,
                                      uint32_t a0, uint32_t a1, uint32_t a2, uint32_t a3,
                                      uint32_t b0, uint32_t b1) {
    asm volatile("mma.sync.aligned.m16n8k16.row.col.f32.bf16.bf16.f32 "
                 "{%0,%1,%2,%3}, {%4,%5,%6,%7}, {%8,%9}, {%0,%1,%2,%3};"
                 : "+f"(c[0]), "+f"(c[1]), "+f"(c[2]), "+f"(c[3])
                 : "r"(a0), "r"(a1), "r"(a2), "r"(a3), "r"(b0), "r"(b1));
}
__device__ __forceinline__ void cp16(uint32_t smem, const void* gmem) {
    asm volatile("cp.async.cg.shared.global [%0], [%1], 16;" :: "r"(smem), "l"(gmem));
}
#define CP_COMMIT() asm volatile("cp.async.commit_group;")
#define CP_WAIT(n)  asm volatile("cp.async.wait_group %0;" :: "n"(n))

// ---------------- shared mma fragment over one 32-k sub-tile (bf16, 64B rows) ----------------
template<int F, int NF2>
__device__ __forceinline__ void compute_tile(const uint4* __restrict__ As,
                                             const uint4* __restrict__ Bs,
                                             float c[2][NF2][4],
                                             int wx, int wy, int g, int t) {
#pragma unroll
    for (int mf = 0; mf < 2; mf++) {
        const int r0 = wx * 32 + mf * 16 + g;
        uint4 Alo = As[r0 * 4 + t];
        uint4 Ahi = As[(r0 + 8) * 4 + t];
#pragma unroll
        for (int nf = 0; nf < NF2; nf++) {
            const int n = wy * (F / 2) + nf * 8 + g;
            uint4 Bv = Bs[n * 4 + t];
            mma16(c[mf][nf], Alo.x, Ahi.x, Alo.y, Ahi.y, Bv.x, Bv.y);
            mma16(c[mf][nf], Alo.z, Ahi.z, Alo.w, Ahi.w, Bv.z, Bv.w);
        }
    }
}

template<int F, int NF2>
__device__ __forceinline__ void store_partials(float* __restrict__ part,
                                               float c[2][NF2][4],
                                               int rowBase, int wx, int wy, int g, int t) {
    float* pbase = part + (size_t)blockIdx.y * N_NODES * F;
#pragma unroll
    for (int mf = 0; mf < 2; mf++) {
        const int r0 = rowBase + wx * 32 + mf * 16 + g;
#pragma unroll
        for (int nf = 0; nf < NF2; nf++) {
            const int col = wy * (F / 2) + nf * 8 + 2 * t;
            *reinterpret_cast<float2*>(pbase + (size_t)r0 * F + col) =
                make_float2(c[mf][nf][0], c[mf][nf][1]);
            *reinterpret_cast<float2*>(pbase + (size_t)(r0 + 8) * F + col) =
                make_float2(c[mf][nf][2], c[mf][nf][3]);
        }
    }
}

// ---------------- layer 1: cp.async fp32 adj -> frag cvt + GEMM + bf16 copy (4 stages) ----------------
template<int F>
__global__ __launch_bounds__(256, 3) void adj_gemm_cvt(const float* __restrict__ adj,
                                                       float* __restrict__ part) {
    constexpr int NF2 = F / 16;
    constexpr int NKT = KSPAN / 32;    // 64
    constexpr int S = 4;
    __shared__ __align__(16) float4 As[S][128 * 8];  // fp32 tile, 16KB/stage
    __shared__ __align__(16) uint4  Bs[S][F * 4];
    constexpr uint32_t A_STRIDE = 128 * 8 * sizeof(float4);
    constexpr uint32_t B_STRIDE = F * 4 * sizeof(uint4);

    const int tid = threadIdx.x;
    const int wid = tid >> 5, lane = tid & 31;
    const int g = lane >> 2, t = lane & 3;
    const int wx = wid >> 1, wy = wid & 1;
    const int rowBase = blockIdx.x * BM;
    const int k0 = blockIdx.y * KSPAN;

    float c[2][NF2][4];
#pragma unroll
    for (int mf = 0; mf < 2; mf++)
#pragma unroll
        for (int nf = 0; nf < NF2; nf++)
#pragma unroll
            for (int e = 0; e < 4; e++) c[mf][nf][e] = 0.f;

    // A: 4 cp16/thread (128 rows x 8 float4-chunks)
    const float4* a_src[4];
    uint32_t a_sm0[4];
#pragma unroll
    for (int i = 0; i < 4; i++) {
        int lin = tid + 256 * i;
        int row = lin >> 3, ch = lin & 7;
        a_src[i] = reinterpret_cast<const float4*>(
            adj + (size_t)(rowBase + row) * N_NODES + k0) + ch;
        a_sm0[i] = smem_u32(&As[0][row * 8 + ch]);
    }
    // B: 1 cp16/thread from blocked layout
    const bool bon = tid < 4 * F;
    const int b_f = bon ? (tid >> 2) : 0, b_jc = tid & 3;
    const uint4* b_base = reinterpret_cast<const uint4*>(g_xwB) + (size_t)(k0 >> 6) * (F * 8);
    const uint32_t b_sm0 = smem_u32(&Bs[0][b_f * 4 + b_jc]);
    const int b_fix = b_f * 8 + b_jc;

    auto issue = [&](int ti, int s) {
#pragma unroll
        for (int i = 0; i < 4; i++) cp16(a_sm0[i] + s * A_STRIDE, a_src[i] + (size_t)ti * 8);
        if (bon) cp16(b_sm0 + s * B_STRIDE,
                      b_base + (size_t)(ti >> 1) * (F * 8) + ((ti & 1) * 4) + b_fix);
        CP_COMMIT();
    };

#pragma unroll
    for (int p = 0; p < S - 1; p++) issue(p, p);

    // copy map: 2 float4-pairs/thread -> 2 STG.128 bf16
    const int cj0 = tid, cj1 = tid + 256;

#pragma unroll 1
    for (int ti = 0; ti < NKT; ti++) {
        const int s = ti % S;
        if (ti + S - 1 < NKT) { CP_WAIT(S - 2); } else { CP_WAIT(0); }
        __syncthreads();
        if (ti + S - 1 < NKT) issue(ti + S - 1, (ti + S - 1) % S);

        // bf16 copy to g_adj16 (from smem)
#pragma unroll
        for (int i = 0; i < 2; i++) {
            int j = (i == 0) ? cj0 : cj1;                 // 0..511
            float4 u = As[s][2 * j], v = As[s][2 * j + 1];
            uint4 p = make_uint4(pack_bf16(u.x, u.y), pack_bf16(u.z, u.w),
                                 pack_bf16(v.x, v.y), pack_bf16(v.z, v.w));
            int row = j >> 2;
            *reinterpret_cast<uint4*>(
                g_adj16 + (size_t)(rowBase + row) * N_NODES + k0 + ti * 32 + (j & 3) * 8) = p;
        }

        // compute: build bf16 fragments from fp32 smem
#pragma unroll
        for (int mf = 0; mf < 2; mf++) {
            const int r0 = wx * 32 + mf * 16 + g;
            float4 a0 = As[s][r0 * 8 + 2 * t],       a1 = As[s][r0 * 8 + 2 * t + 1];
            float4 h0 = As[s][(r0 + 8) * 8 + 2 * t], h1 = As[s][(r0 + 8) * 8 + 2 * t + 1];
            uint32_t alo0 = pack_bf16(a0.x, a0.y), alo1 = pack_bf16(a0.z, a0.w);
            uint32_t alo2 = pack_bf16(a1.x, a1.y), alo3 = pack_bf16(a1.z, a1.w);
            uint32_t ahi0 = pack_bf16(h0.x, h0.y), ahi1 = pack_bf16(h0.z, h0.w);
            uint32_t ahi2 = pack_bf16(h1.x, h1.y), ahi3 = pack_bf16(h1.z, h1.w);
#pragma unroll
            for (int nf = 0; nf < NF2; nf++) {
                const int n = wy * (F / 2) + nf * 8 + g;
                uint4 Bv = Bs[s][n * 4 + t];
                mma16(c[mf][nf], alo0, ahi0, alo1, ahi1, Bv.x, Bv.y);
                mma16(c[mf][nf], alo2, ahi2, alo3, ahi3, Bv.z, Bv.w);
            }
        }
    }
    store_partials<F, NF2>(part, c, rowBase, wx, wy, g, t);
}

// ---------------- layers 2/3: bf16 adj, deep cp.async pipeline, BK=32 ----------------
// F=48: S=5, 4 CTAs/SM (launch_bounds regs<=64). F=64: S=6, 3 CTAs/SM, deeper pipeline.
template<int F, int S, int MINB>
__global__ __launch_bounds__(256, MINB) void adj_gemm_cp(float* __restrict__ part) {
    constexpr int NF2 = F / 16;
    constexpr int NKT = KSPAN / 32;    // 64
    __shared__ __align__(16) uint4 As[S][BM * 4];   // 8KB/stage
    __shared__ __align__(16) uint4 Bs[S][F * 4];
    constexpr uint32_t A_STRIDE = BM * 4 * sizeof(uint4);
    constexpr uint32_t B_STRIDE = F * 4 * sizeof(uint4);

    const int tid = threadIdx.x;
    const int wid = tid >> 5, lane = tid & 31;
    const int g = lane >> 2, t = lane & 3;
    const int wx = wid >> 1, wy = wid & 1;
    const int rowBase = blockIdx.x * BM;
    const int k0 = blockIdx.y * KSPAN;

    float c[2][NF2][4];
#pragma unroll
    for (int mf = 0; mf < 2; mf++)
#pragma unroll
        for (int nf = 0; nf < NF2; nf++)
#pragma unroll
            for (int e = 0; e < 4; e++) c[mf][nf][e] = 0.f;

    // A: 2 cp16/thread (128 rows x 4 chunks of 16B bf16)
    const __nv_bfloat16* a_src[2];
    uint32_t a_sm0[2];
#pragma unroll
    for (int i = 0; i < 2; i++) {
        int lin = tid + 256 * i;
        int row = lin >> 2, ch = lin & 3;
        a_src[i] = g_adj16 + (size_t)(rowBase + row) * N_NODES + k0 + 8 * ch;
        a_sm0[i] = smem_u32(&As[0][row * 4 + ch]);
    }
    // B: 1 cp16/thread
    const bool bon = tid < 4 * F;
    const int b_f = bon ? (tid >> 2) : 0, b_jc = tid & 3;
    const uint4* b_base = reinterpret_cast<const uint4*>(g_xwB) + (size_t)(k0 >> 6) * (F * 8);
    const uint32_t b_sm0 = smem_u32(&Bs[0][b_f * 4 + b_jc]);
    const int b_fix = b_f * 8 + b_jc;

    auto issue = [&](int ti, int s) {
#pragma unroll
        for (int i = 0; i < 2; i++) cp16(a_sm0[i] + s * A_STRIDE, a_src[i] + (size_t)ti * 32);
        if (bon) cp16(b_sm0 + s * B_STRIDE,
                      b_base + (size_t)(ti >> 1) * (F * 8) + ((ti & 1) * 4) + b_fix);
        CP_COMMIT();
    };

#pragma unroll
    for (int p = 0; p < S - 1; p++) issue(p, p);

#pragma unroll 1
    for (int ti = 0; ti < NKT; ti++) {
        const int s = ti % S;
        if (ti + S - 1 < NKT) { CP_WAIT(S - 2); } else { CP_WAIT(0); }
        __syncthreads();
        if (ti + S - 1 < NKT) issue(ti + S - 1, (ti + S - 1) % S);
        compute_tile<F, NF2>(As[s], Bs[s], c, wx, wy, g, t);
    }
    store_partials<F, NF2>(part, c, rowBase, wx, wy, g, t);
}

// ---------------- fused: xw1 = x @ W1, packed into blocked B layout ----------------
__global__ __launch_bounds__(256) void fuse_first(const float* __restrict__ x,
                                                  const float* __restrict__ W1) {
    __shared__ float Ws[128 * 32];
    __shared__ uint32_t stage[32 * 32];
    const int tid = threadIdx.x;
    for (int i = tid; i < 128 * 32 / 4; i += 256)
        reinterpret_cast<float4*>(Ws)[i] = reinterpret_cast<const float4*>(W1)[i];
    __syncthreads();

    const int rp = tid >> 3, cgi = tid & 7;
    const int c0 = cgi * 4;
    const int r0 = blockIdx.x * 64 + 2 * rp;
    const float4* x0 = reinterpret_cast<const float4*>(x + (size_t)r0 * 128);
    const float4* x1 = reinterpret_cast<const float4*>(x + (size_t)(r0 + 1) * 128);
    float acc0[4] = {0.f, 0.f, 0.f, 0.f}, acc1[4] = {0.f, 0.f, 0.f, 0.f};
#pragma unroll 8
    for (int k4 = 0; k4 < 32; k4++) {
        float4 a = __ldg(&x0[k4]), b = __ldg(&x1[k4]);
#pragma unroll
        for (int e = 0; e < 4; e++) {
            float ae = (e == 0) ? a.x : (e == 1) ? a.y : (e == 2) ? a.z : a.w;
            float be = (e == 0) ? b.x : (e == 1) ? b.y : (e == 2) ? b.z : b.w;
            float4 wv = *reinterpret_cast<const float4*>(&Ws[(k4 * 4 + e) * 32 + c0]);
            acc0[0] += ae * wv.x; acc0[1] += ae * wv.y; acc0[2] += ae * wv.z; acc0[3] += ae * wv.w;
            acc1[0] += be * wv.x; acc1[1] += be * wv.y; acc1[2] += be * wv.z; acc1[3] += be * wv.w;
        }
    }
#pragma unroll
    for (int cc = 0; cc < 4; cc++)
        stage[(c0 + cc) * 32 + rp] = pack_bf16(acc0[cc], acc1[cc]);
    __syncthreads();
    uint4* out = reinterpret_cast<uint4*>(g_xwB + blockIdx.x * 32 * 32);
    out[tid] = reinterpret_cast<const uint4*>(stage)[tid];
}

// ---------------- fused: combine split-K + bias + relu + @W_next + pack to B layout ----------------
template<int FI, int FO>
__global__ __launch_bounds__(256) void fuse_next(const float* __restrict__ part,
                                                 const float* __restrict__ bias,
                                                 const float* __restrict__ W) {
    __shared__ float Ws[FI * FO];
    __shared__ float hs[64 * FI];
    __shared__ uint32_t stage[FO * 32];
    const int tid = threadIdx.x;
    for (int i = tid; i < FI * FO / 4; i += 256)
        reinterpret_cast<float4*>(Ws)[i] = reinterpret_cast<const float4*>(W)[i];

    {
        const int row = tid >> 2, q = tid & 3;
        const int f0 = q * (FI / 4);
        const int gr = blockIdx.x * 64 + row;
        float acc[FI / 4];
#pragma unroll
        for (int j = 0; j < FI / 4; j++) acc[j] = bias[f0 + j];
#pragma unroll
        for (int sk = 0; sk < SPLITK; sk++) {
            const float* p = part + ((size_t)sk * N_NODES + gr) * FI + f0;
#pragma unroll
            for (int j4 = 0; j4 < FI / 16; j4++) {
                float4 v = *reinterpret_cast<const float4*>(p + 4 * j4);
                acc[j4 * 4 + 0] += v.x; acc[j4 * 4 + 1] += v.y;
                acc[j4 * 4 + 2] += v.z; acc[j4 * 4 + 3] += v.w;
            }
        }
#pragma unroll
        for (int j = 0; j < FI / 4; j++) hs[row * FI + f0 + j] = fmaxf(acc[j], 0.f);
    }
    __syncthreads();

    {
        const int rp = tid >> 3, cgi = tid & 7;
        const int c0 = cgi * (FO / 8);
        float a0c[FO / 8], a1c[FO / 8];
#pragma unroll
        for (int cc = 0; cc < FO / 8; cc++) { a0c[cc] = 0.f; a1c[cc] = 0.f; }
#pragma unroll 4
        for (int k = 0; k < FI; k++) {
            float a0 = hs[(2 * rp) * FI + k];
            float a1 = hs[(2 * rp + 1) * FI + k];
#pragma unroll
            for (int cc = 0; cc < FO / 8; cc++) {
                float w = Ws[k * FO + c0 + cc];
                a0c[cc] += a0 * w; a1c[cc] += a1 * w;
            }
        }
#pragma unroll
        for (int cc = 0; cc < FO / 8; cc++)
            stage[(c0 + cc) * 32 + rp] = pack_bf16(a0c[cc], a1c[cc]);
    }
    __syncthreads();
    uint4* out = reinterpret_cast<uint4*>(g_xwB + blockIdx.x * FO * 32);
#pragma unroll
    for (int i = tid; i < FO * 8; i += 256)
        out[i] = reinterpret_cast<const uint4*>(stage)[i];
}

// ---------------- layer-3 combine + deterministic column reduction (F=64) ----------------
__global__ __launch_bounds__(256) void combine_reduce(const float* __restrict__ part,
                                                      const float* __restrict__ bias,
                                                      float* __restrict__ colsum) {
    __shared__ float red[4][64];
    const int tid = threadIdx.x;
    const int c = tid & 63, rg = tid >> 6;
    const int rowBase = blockIdx.x * 64;
    const float b = bias[c];
    float s = 0.f;
#pragma unroll 4
    for (int i = 0; i < 16; i++) {
        const int row = rowBase + rg + 4 * i;
        float v = 0.f;
#pragma unroll
        for (int sk = 0; sk < SPLITK; sk++)
            v += part[((size_t)sk * N_NODES + row) * 64 + c];
        s += fmaxf(v + b, 0.f);
    }
    red[rg][c] = s;
    __syncthreads();
    if (rg == 0)
        colsum[blockIdx.x * 64 + c] = red[0][c] + red[1][c] + red[2][c] + red[3][c];
}

// ---------------- readout + MLP head + softmax ----------------
__global__ void head_kernel(const float* __restrict__ colsum,
                            const float* __restrict__ fcW1, const float* __restrict__ fcb1,
                            const float* __restrict__ fcW2, const float* __restrict__ fcb2,
                            float* __restrict__ out) {
    __shared__ float mean_s[64];
    __shared__ float z1_s[32];
    int t = threadIdx.x;  // 64 threads
    float s = 0.f;
    for (int b = 0; b < 256; b++) s += colsum[b * 64 + t];
    mean_s[t] = s * (1.0f / N_NODES);
    __syncthreads();
    if (t < 32) {
        float a = 0.f;
#pragma unroll
        for (int c = 0; c < 64; c++) a += mean_s[c] * fcW1[c * 32 + t];
        z1_s[t] = fmaxf(a + fcb1[t], 0.f);
    }
    __syncthreads();
    if (t == 0) {
        float z0 = fcb2[0], z1 = fcb2[1];
#pragma unroll
        for (int j = 0; j < 32; j++) {
            z0 += z1_s[j] * fcW2[j * 2 + 0];
            z1 += z1_s[j] * fcW2[j * 2 + 1];
        }
        float m  = fmaxf(z0, z1);
        float e0 = expf(z0 - m), e1 = expf(z1 - m);
        float inv = 1.0f / (e0 + e1);
        out[0] = e0 * inv;
        out[1] = e1 * inv;
    }
}

// ---------------- launch ----------------
extern "C" void kernel_launch(void* const* d_in, const int* in_sizes, int n_in,
                              void* d_out, int out_size) {
    const float* x    = (const float*)d_in[0];
    const float* adj  = (const float*)d_in[1];
    // d_in[2] = idx_map (unused by the reference)
    const float* W1   = (const float*)d_in[3];
    const float* b1   = (const float*)d_in[4];
    const float* W2   = (const float*)d_in[5];
    const float* b2   = (const float*)d_in[6];
    const float* W3   = (const float*)d_in[7];
    const float* b3   = (const float*)d_in[8];
    const float* fcW1 = (const float*)d_in[9];
    const float* fcb1 = (const float*)d_in[10];
    const float* fcW2 = (const float*)d_in[11];
    const float* fcb2 = (const float*)d_in[12];
    float* out = (float*)d_out;

    float *part, *colsum;
    cudaGetSymbolAddress((void**)&part, g_part);
    cudaGetSymbolAddress((void**)&colsum, g_colsum);

    dim3 agrid(N_NODES / BM, SPLITK);

    fuse_first<<<256, 256>>>(x, W1);
    adj_gemm_cvt<32><<<agrid, 256>>>(adj, part);
    fuse_next<32, 48><<<256, 256>>>(part, b1, W2);
    adj_gemm_cp<48, 5, 4><<<agrid, 256>>>(part);
    fuse_next<48, 64><<<256, 256>>>(part, b2, W3);
    adj_gemm_cp<64, 6, 3><<<agrid, 256>>>(part);
    combine_reduce<<<256, 256>>>(part, b3, colsum);
    head_kernel<<<1, 64>>>(colsum, fcW1, fcb1, fcW2, fcb2, out);
}